// round 7
// baseline (speedup 1.0000x reference)
#include <cuda_runtime.h>
#include <cuda_bf16.h>
#include <mma.h>
#include <math.h>
#include <stdint.h>

using namespace nvcuda;

#define E_DIM 2048
#define B_SZ 2
#define S_LEN 2048
#define NH 16
#define DH 128
#define LDIM 64
#define M_ROWS 4096    /* B*S */

// ---------------- scratch (device globals; no runtime allocation) ----------------
__device__ __nv_bfloat16 g_Ahi[(size_t)M_ROWS * E_DIM];
__device__ __nv_bfloat16 g_Alo[(size_t)M_ROWS * E_DIM];
__device__ __nv_bfloat16 g_Qhi[(size_t)M_ROWS * E_DIM];
__device__ __nv_bfloat16 g_Qlo[(size_t)M_ROWS * E_DIM];
__device__ __nv_bfloat16 g_Khi[(size_t)M_ROWS * E_DIM];
__device__ __nv_bfloat16 g_Klo[(size_t)M_ROWS * E_DIM];
__device__ float g_V[(size_t)M_ROWS * E_DIM];
__device__ float g_QL[(size_t)B_SZ * NH * S_LEN * LDIM];
__device__ float g_KL[(size_t)B_SZ * NH * S_LEN * LDIM];
__device__ __nv_bfloat16 g_AThi[(size_t)B_SZ * NH * S_LEN * DH];
__device__ __nv_bfloat16 g_ATlo[(size_t)B_SZ * NH * S_LEN * DH];
__device__ __nv_bfloat16 g_W3hi[(size_t)3 * E_DIM * E_DIM];
__device__ __nv_bfloat16 g_W3lo[(size_t)3 * E_DIM * E_DIM];
__device__ __nv_bfloat16 g_Wthi[(size_t)E_DIM * E_DIM];
__device__ __nv_bfloat16 g_Wtlo[(size_t)E_DIM * E_DIM];
__device__ __nv_bfloat16 g_Wmhi[DH * DH];
__device__ __nv_bfloat16 g_Wmlo[DH * DH];
__device__ __nv_bfloat16 g_Wlhi[2 * LDIM * DH];
__device__ __nv_bfloat16 g_Wllo[2 * LDIM * DH];

__device__ __forceinline__ float gelu_tanh(float x) {
    const float c = 0.7978845608028654f;
    float x3 = x * x * x;
    return 0.5f * x * (1.f + tanhf(c * (x + 0.044715f * x3)));
}

__device__ __forceinline__ uint32_t smem_u32(const void* p) {
    uint32_t a;
    asm("{ .reg .u64 t; cvta.to.shared.u64 t, %1; cvt.u32.u64 %0, t; }" : "=r"(a) : "l"(p));
    return a;
}
#define CP_ASYNC16(dst, src) \
    asm volatile("cp.async.cg.shared.global [%0], [%1], 16;" :: "r"(dst), "l"(src))
#define CP_COMMIT() asm volatile("cp.async.commit_group;" ::: "memory")
#define CP_WAIT(n)  asm volatile("cp.async.wait_group %0;" :: "n"(n) : "memory")

__device__ __forceinline__ float tf32r(float x) {
    uint32_t u;
    asm("cvt.rna.tf32.f32 %0, %1;" : "=r"(u) : "f"(x));
    return __uint_as_float(u);
}

#define MMA_TF32(c, a0, a1, a2, a3, b0, b1) \
    asm volatile("mma.sync.aligned.m16n8k8.row.col.f32.tf32.tf32.f32 " \
        "{%0,%1,%2,%3}, {%4,%5,%6,%7}, {%8,%9}, {%0,%1,%2,%3};" \
        : "+f"((c)[0]), "+f"((c)[1]), "+f"((c)[2]), "+f"((c)[3]) \
        : "r"(a0), "r"(a1), "r"(a2), "r"(a3), "r"(b0), "r"(b1))

__device__ __forceinline__ void bf16_split(float v, __nv_bfloat16& h, __nv_bfloat16& l) {
    h = __float2bfloat16(v);
    l = __float2bfloat16(v - __bfloat162float(h));
}

// ================= prepass: bf16 hi/lo split (row-major) =================
__global__ __launch_bounds__(256) void xsplit_kernel(
    const float* __restrict__ src, __nv_bfloat16* __restrict__ hi, __nv_bfloat16* __restrict__ lo, int n4)
{
    int i = blockIdx.x * 256 + threadIdx.x;
    if (i >= n4) return;
    float4 v = reinterpret_cast<const float4*>(src)[i];
    __nv_bfloat16 h0, h1, h2, h3, l0, l1, l2, l3;
    bf16_split(v.x, h0, l0); bf16_split(v.y, h1, l1);
    bf16_split(v.z, h2, l2); bf16_split(v.w, h3, l3);
    __nv_bfloat162* ph = reinterpret_cast<__nv_bfloat162*>(hi) + i * 2;
    __nv_bfloat162* pl = reinterpret_cast<__nv_bfloat162*>(lo) + i * 2;
    ph[0] = __nv_bfloat162(h0, h1); ph[1] = __nv_bfloat162(h2, h3);
    pl[0] = __nv_bfloat162(l0, l1); pl[1] = __nv_bfloat162(l2, l3);
}

// ===== prepass: 4 weights [K,N] -> [N,K] bf16 transpose-split in ONE launch =====
__global__ __launch_bounds__(256) void wsplit4_kernel(
    const float* __restrict__ Wq, const float* __restrict__ Wk,
    const float* __restrict__ Wv, const float* __restrict__ Wo,
    __nv_bfloat16* __restrict__ W3hi, __nv_bfloat16* __restrict__ W3lo,
    __nv_bfloat16* __restrict__ Wthi, __nv_bfloat16* __restrict__ Wtlo)
{
    __shared__ float t[32][33];
    int id = blockIdx.z;
    const float* W = (id == 0) ? Wq : (id == 1) ? Wk : (id == 2) ? Wv : Wo;
    __nv_bfloat16* hi = (id < 3) ? W3hi + (size_t)id * E_DIM * E_DIM : Wthi;
    __nv_bfloat16* lo = (id < 3) ? W3lo + (size_t)id * E_DIM * E_DIM : Wtlo;

    int tx = threadIdx.x & 31, ty = threadIdx.x >> 5;
    int k0 = blockIdx.y * 32, n0 = blockIdx.x * 32;
#pragma unroll
    for (int j = 0; j < 4; j++)
        t[ty + j * 8][tx] = W[(size_t)(k0 + ty + j * 8) * E_DIM + n0 + tx];
    __syncthreads();
#pragma unroll
    for (int j = 0; j < 4; j++) {
        float v = t[tx][ty + j * 8];
        __nv_bfloat16 h, l;
        bf16_split(v, h, l);
        size_t o = (size_t)(n0 + ty + j * 8) * E_DIM + k0 + tx;
        hi[o] = h; lo[o] = l;
    }
}

// ====== prepass: small weights (Wm [128,128], Wql/Wkl [128,64]) -> [N,K] hi/lo ======
__global__ __launch_bounds__(256) void smallw_kernel(
    const float* __restrict__ Wm, const float* __restrict__ Wql, const float* __restrict__ Wkl,
    __nv_bfloat16* __restrict__ Wmhi, __nv_bfloat16* __restrict__ Wmlo,
    __nv_bfloat16* __restrict__ Wlhi, __nv_bfloat16* __restrict__ Wllo)
{
    int id = blockIdx.x;
    if (id == 0) {
        for (int i = threadIdx.x; i < DH * DH; i += 256) {
            int n = i >> 7, k = i & 127;
            __nv_bfloat16 h, l;
            bf16_split(Wm[k * DH + n], h, l);
            Wmhi[n * DH + k] = h; Wmlo[n * DH + k] = l;
        }
    } else {
        const float* W = (id == 1) ? Wql : Wkl;
        __nv_bfloat16* hi = Wlhi + (id - 1) * LDIM * DH;
        __nv_bfloat16* lo = Wllo + (id - 1) * LDIM * DH;
        for (int i = threadIdx.x; i < LDIM * DH; i += 256) {
            int n = i >> 7, k = i & 127;
            __nv_bfloat16 h, l;
            bf16_split(W[k * LDIM + n], h, l);
            hi[n * DH + k] = h; lo[n * DH + k] = l;
        }
    }
}

// ============ bf16 3-term GEMM, CTA 256x128, warp tile 64x64, K-chunk 32 ============
#define GN_STRIDE 40                      /* bf16 elems per smem row (32 + 8 pad) */
#define GN_A_B (256 * GN_STRIDE * 2)      /* 20480 B */
#define GN_W_B (128 * GN_STRIDE * 2)      /* 10240 B */
#define GN_OFF_AL GN_A_B
#define GN_OFF_WH (2 * GN_A_B)
#define GN_OFF_WL (2 * GN_A_B + GN_W_B)
#define GN_STAGE (2 * GN_A_B + 2 * GN_W_B)   /* 61440 B */
#define GN_SMEM (2 * GN_STAGE)               /* 122880 B */

// loader: 12 cp.async per thread per k-chunk
#define GN_LOAD(kcn, st)                                                            \
    {                                                                               \
        int rA = tid >> 2, cA = tid & 3;                                            \
        _Pragma("unroll")                                                           \
        for (int q = 0; q < 4; q++) {                                               \
            int r = q * 64 + rA;                                                    \
            uint32_t dp = sb + (st) * GN_STAGE + r * (GN_STRIDE * 2) + cA * 16;     \
            CP_ASYNC16(dp, Ahi + (size_t)(m0 + r) * E_DIM + (kcn) * 32 + cA * 8);   \
            CP_ASYNC16(dp + GN_OFF_AL, Alo + (size_t)(m0 + r) * E_DIM + (kcn) * 32 + cA * 8); \
        }                                                                           \
        _Pragma("unroll")                                                           \
        for (int q = 0; q < 2; q++) {                                               \
            int r = q * 64 + rA;                                                    \
            uint32_t dp = sb + (st) * GN_STAGE + GN_OFF_WH + r * (GN_STRIDE * 2) + cA * 16; \
            CP_ASYNC16(dp, Whi + (size_t)(n0 + r) * E_DIM + (kcn) * 32 + cA * 8);   \
            CP_ASYNC16(dp + GN_W_B, Wlo + (size_t)(n0 + r) * E_DIM + (kcn) * 32 + cA * 8);  \
        }                                                                           \
    }

#define GN_MAINLOOP()                                                               \
    GN_LOAD(0, 0)                                                                   \
    CP_COMMIT();                                                                    \
    for (int kc = 0; kc < 64; kc++) {                                               \
        int s = kc & 1;                                                             \
        if (kc < 63) {                                                              \
            GN_LOAD(kc + 1, s ^ 1)                                                  \
            CP_COMMIT();                                                            \
            CP_WAIT(1);                                                             \
        } else {                                                                    \
            CP_WAIT(0);                                                             \
        }                                                                           \
        __syncthreads();                                                            \
        const __nv_bfloat16* Ah = reinterpret_cast<const __nv_bfloat16*>(smem + s * GN_STAGE); \
        const __nv_bfloat16* Al = reinterpret_cast<const __nv_bfloat16*>(smem + s * GN_STAGE + GN_OFF_AL); \
        const __nv_bfloat16* Wh = reinterpret_cast<const __nv_bfloat16*>(smem + s * GN_STAGE + GN_OFF_WH); \
        const __nv_bfloat16* Wl = reinterpret_cast<const __nv_bfloat16*>(smem + s * GN_STAGE + GN_OFF_WL); \
        _Pragma("unroll")                                                           \
        for (int ks = 0; ks < 2; ks++) {                                            \
            wmma::fragment<wmma::matrix_a, 16, 16, 16, __nv_bfloat16, wmma::row_major> ah[4], al2[4]; \
            _Pragma("unroll")                                                       \
            for (int i = 0; i < 4; i++) {                                           \
                wmma::load_matrix_sync(ah[i], &Ah[(wr * 64 + i * 16) * GN_STRIDE + ks * 16], GN_STRIDE); \
                wmma::load_matrix_sync(al2[i], &Al[(wr * 64 + i * 16) * GN_STRIDE + ks * 16], GN_STRIDE); \
            }                                                                       \
            _Pragma("unroll")                                                       \
            for (int j = 0; j < 4; j++) {                                           \
                wmma::fragment<wmma::matrix_b, 16, 16, 16, __nv_bfloat16, wmma::col_major> bh, bl; \
                wmma::load_matrix_sync(bh, &Wh[(wc * 64 + j * 16) * GN_STRIDE + ks * 16], GN_STRIDE); \
                wmma::load_matrix_sync(bl, &Wl[(wc * 64 + j * 16) * GN_STRIDE + ks * 16], GN_STRIDE); \
                _Pragma("unroll")                                                   \
                for (int i = 0; i < 4; i++) {                                       \
                    wmma::mma_sync(cf[i][j], ah[i], bl, cf[i][j]);                  \
                    wmma::mma_sync(cf[i][j], al2[i], bh, cf[i][j]);                 \
                    wmma::mma_sync(cf[i][j], ah[i], bh, cf[i][j]);                  \
                }                                                                   \
            }                                                                       \
        }                                                                           \
        __syncthreads();                                                            \
    }

// --- fused QKV variant: epilogue routes Q/K -> bf16 hi/lo, V -> tf32 float ---
__global__ __launch_bounds__(256) void gemm_qkv_kernel(
    const __nv_bfloat16* __restrict__ Ahi, const __nv_bfloat16* __restrict__ Alo,
    const __nv_bfloat16* __restrict__ Whi, const __nv_bfloat16* __restrict__ Wlo,
    const float* __restrict__ bq, const float* __restrict__ bk, const float* __restrict__ bv,
    __nv_bfloat16* __restrict__ Qhi, __nv_bfloat16* __restrict__ Qlo,
    __nv_bfloat16* __restrict__ Khi, __nv_bfloat16* __restrict__ Klo,
    float* __restrict__ Vout)
{
    extern __shared__ char smem[];
    uint32_t sb = smem_u32(smem);
    int tid = threadIdx.x, wid = tid >> 5, lane = tid & 31;
    int wr = wid >> 1, wc = wid & 1;            // 4 x 2 warps, tile 64x64
    int m0 = blockIdx.y * 256, n0 = blockIdx.x * 128;

    wmma::fragment<wmma::accumulator, 16, 16, 16, float> cf[4][4];
#pragma unroll
    for (int i = 0; i < 4; i++)
#pragma unroll
        for (int j = 0; j < 4; j++) wmma::fill_fragment(cf[i][j], 0.f);

    GN_MAINLOOP()

    int which = n0 >> 11;           // 0=Q 1=K 2=V
    int nbase = n0 & 2047;
    const float* bptr = (which == 0) ? bq : ((which == 1) ? bk : bv);
    __nv_bfloat16* Hp = (which == 1) ? Khi : Qhi;
    __nv_bfloat16* Lp = (which == 1) ? Klo : Qlo;

    float* scratch = reinterpret_cast<float*>(smem) + wid * 320;
#pragma unroll
    for (int i = 0; i < 4; i++)
#pragma unroll
        for (int j = 0; j < 4; j++) {
            wmma::store_matrix_sync(scratch, cf[i][j], 20, wmma::mem_row_major);
            __syncwarp();
            int gr0 = m0 + wr * 64 + i * 16;
            int gcl = nbase + wc * 64 + j * 16;
#pragma unroll
            for (int e = lane; e < 256; e += 32) {
                int rr = e >> 4, cc = e & 15;
                float v = scratch[rr * 20 + cc] + bptr[gcl + cc];
                size_t o = (size_t)(gr0 + rr) * E_DIM + gcl + cc;
                if (which == 2) {
                    Vout[o] = tf32r(v);
                } else {
                    __nv_bfloat16 h, l;
                    bf16_split(v, h, l);
                    Hp[o] = h; Lp[o] = l;
                }
            }
            __syncwarp();
        }
}

// --- output GEMM: plain float epilogue ---
__global__ __launch_bounds__(256) void gemm_bf3_kernel(
    const __nv_bfloat16* __restrict__ Ahi, const __nv_bfloat16* __restrict__ Alo,
    const __nv_bfloat16* __restrict__ Whi, const __nv_bfloat16* __restrict__ Wlo,
    const float* __restrict__ bias, float* __restrict__ C)
{
    extern __shared__ char smem[];
    uint32_t sb = smem_u32(smem);
    int tid = threadIdx.x, wid = tid >> 5, lane = tid & 31;
    int wr = wid >> 1, wc = wid & 1;
    int m0 = blockIdx.y * 256, n0 = blockIdx.x * 128;

    wmma::fragment<wmma::accumulator, 16, 16, 16, float> cf[4][4];
#pragma unroll
    for (int i = 0; i < 4; i++)
#pragma unroll
        for (int j = 0; j < 4; j++) wmma::fill_fragment(cf[i][j], 0.f);

    GN_MAINLOOP()

    float* scratch = reinterpret_cast<float*>(smem) + wid * 320;
#pragma unroll
    for (int i = 0; i < 4; i++)
#pragma unroll
        for (int j = 0; j < 4; j++) {
            wmma::store_matrix_sync(scratch, cf[i][j], 20, wmma::mem_row_major);
            __syncwarp();
            int gr0 = m0 + wr * 64 + i * 16;
            int gc0 = n0 + wc * 64 + j * 16;
#pragma unroll
            for (int e = lane; e < 256; e += 32) {
                int rr = e >> 4, cc = e & 15;
                float v = scratch[rr * 20 + cc] + bias[gc0 + cc];
                C[(size_t)(gr0 + rr) * E_DIM + gc0 + cc] = v;
            }
            __syncwarp();
        }
}

// ---------------- latent projection: bf16 3-term, elu+1, scale-fold, tf32 round ----------------
#define LB_AEL (128 * 136)
#define LB_BEL (64 * 136)
#define LB_SMEM ((2 * LB_AEL + 2 * LB_BEL) * 2)

__global__ __launch_bounds__(256) void lat_bf16_kernel(
    const __nv_bfloat16* __restrict__ Qhi, const __nv_bfloat16* __restrict__ Qlo,
    const __nv_bfloat16* __restrict__ Khi, const __nv_bfloat16* __restrict__ Klo,
    const __nv_bfloat16* __restrict__ Wlhi, const __nv_bfloat16* __restrict__ Wllo,
    const float* __restrict__ bql, const float* __restrict__ bkl,
    float* __restrict__ QL, float* __restrict__ KL)
{
    extern __shared__ __nv_bfloat16 smb[];
    __nv_bfloat16* Ah = smb;
    __nv_bfloat16* Al = Ah + LB_AEL;
    __nv_bfloat16* Bh = Al + LB_AEL;
    __nv_bfloat16* Bl = Bh + LB_BEL;

    int tid = threadIdx.x, w = tid >> 5, lane = tid & 31;
    int wr = w >> 1, wc = w & 1;
    int h = blockIdx.y, which = blockIdx.z;
    int m0 = blockIdx.x * 128;

    const __nv_bfloat16* Ash = which ? Khi : Qhi;
    const __nv_bfloat16* Asl = which ? Klo : Qlo;
    const __nv_bfloat16* Wsh = Wlhi + which * LDIM * DH;
    const __nv_bfloat16* Wsl = Wllo + which * LDIM * DH;
    const float* bl = which ? bkl : bql;
    float* C = which ? KL : QL;

#pragma unroll
    for (int i = 0; i < 8; i++) {
        int idx = i * 256 + tid;
        int r = idx >> 4, c8 = idx & 15;
        *reinterpret_cast<uint4*>(&Ah[r * 136 + c8 * 8]) =
            *reinterpret_cast<const uint4*>(&Ash[(size_t)(m0 + r) * E_DIM + h * DH + c8 * 8]);
        *reinterpret_cast<uint4*>(&Al[r * 136 + c8 * 8]) =
            *reinterpret_cast<const uint4*>(&Asl[(size_t)(m0 + r) * E_DIM + h * DH + c8 * 8]);
    }
#pragma unroll
    for (int i = 0; i < 4; i++) {
        int idx = i * 256 + tid;
        int r = idx >> 4, c8 = idx & 15;
        *reinterpret_cast<uint4*>(&Bh[r * 136 + c8 * 8]) =
            *reinterpret_cast<const uint4*>(&Wsh[r * DH + c8 * 8]);
        *reinterpret_cast<uint4*>(&Bl[r * 136 + c8 * 8]) =
            *reinterpret_cast<const uint4*>(&Wsl[r * DH + c8 * 8]);
    }
    __syncthreads();

    wmma::fragment<wmma::accumulator, 16, 16, 16, float> cf[2][2];
#pragma unroll
    for (int i = 0; i < 2; i++)
#pragma unroll
        for (int j = 0; j < 2; j++) wmma::fill_fragment(cf[i][j], 0.f);

#pragma unroll
    for (int ks = 0; ks < 8; ks++) {
        wmma::fragment<wmma::matrix_a, 16, 16, 16, __nv_bfloat16, wmma::row_major> ah[2], al2[2];
        wmma::fragment<wmma::matrix_b, 16, 16, 16, __nv_bfloat16, wmma::col_major> bh[2], bl2[2];
#pragma unroll
        for (int i = 0; i < 2; i++) {
            wmma::load_matrix_sync(ah[i], &Ah[(wr * 32 + i * 16) * 136 + ks * 16], 136);
            wmma::load_matrix_sync(al2[i], &Al[(wr * 32 + i * 16) * 136 + ks * 16], 136);
        }
#pragma unroll
        for (int j = 0; j < 2; j++) {
            wmma::load_matrix_sync(bh[j], &Bh[(wc * 32 + j * 16) * 136 + ks * 16], 136);
            wmma::load_matrix_sync(bl2[j], &Bl[(wc * 32 + j * 16) * 136 + ks * 16], 136);
        }
#pragma unroll
        for (int i = 0; i < 2; i++)
#pragma unroll
            for (int j = 0; j < 2; j++) {
                wmma::mma_sync(cf[i][j], ah[i], bl2[j], cf[i][j]);
                wmma::mma_sync(cf[i][j], al2[i], bh[j], cf[i][j]);
                wmma::mma_sync(cf[i][j], ah[i], bh[j], cf[i][j]);
            }
    }
    __syncthreads();

    float* scratch = reinterpret_cast<float*>(smb) + w * 320;
    float qscale = which ? 1.0f : 0.125f;
#pragma unroll
    for (int i = 0; i < 2; i++)
#pragma unroll
        for (int j = 0; j < 2; j++) {
            wmma::store_matrix_sync(scratch, cf[i][j], 20, wmma::mem_row_major);
            __syncwarp();
#pragma unroll
            for (int e = lane; e < 256; e += 32) {
                int rr = e >> 4, cc = e & 15;
                int gr = m0 + wr * 32 + i * 16 + rr;
                int gc = wc * 32 + j * 16 + cc;
                float v = scratch[rr * 20 + cc] + bl[gc];
                v = (v > 0.f) ? (v + 1.f) : expf(v);
                v = tf32r(v * qscale);
                int b = gr >> 11;
                int s = gr & 2047;
                C[((size_t)(b * NH + h) * S_LEN + s) * LDIM + gc] = v;
            }
            __syncwarp();
        }
}

// ================ single-pass flash attention (raw mma.sync tf32) ================
#define AT_QS 0
#define AT_KS (128 * 68)
#define AT_VS (AT_KS + 2 * 64 * 68)
#define AT_PS (AT_VS + 2 * 64 * 136)
#define AT_TOT (AT_PS + 128 * 68)
#define AT_SMEM_B (AT_TOT * 4)

__global__ __launch_bounds__(256) void attn2_kernel(
    const float* __restrict__ QL, const float* __restrict__ KL,
    const float* __restrict__ V,
    __nv_bfloat16* __restrict__ OUThi, __nv_bfloat16* __restrict__ OUTlo)
{
    extern __shared__ float sm[];
    float* qs  = sm;
    float* ksb = sm + AT_KS;
    float* vsb = sm + AT_VS;
    float* Ps  = sm + AT_PS;
    uint32_t sbase = smem_u32(sm);

    int tid = threadIdx.x, w = tid >> 5, lane = tid & 31;
    int g = lane >> 2, t = lane & 3;
    int wrow = w * 16;
    int qb = blockIdx.x, h = blockIdx.y, b = blockIdx.z;
    int bh = b * NH + h;

    {
        const float* qsrc = QL + ((size_t)bh * S_LEN + qb * 128) * LDIM;
#pragma unroll
        for (int i = 0; i < 8; i++) {
            int idx = i * 256 + tid;
            int r = idx >> 4, c4 = idx & 15;
            float4 v4 = *reinterpret_cast<const float4*>(&qsrc[r * LDIM + c4 * 4]);
            *reinterpret_cast<float4*>(&qs[r * 68 + c4 * 4]) = v4;
        }
    }

#define AT_PREFETCH(ci, bf)                                                           \
    {                                                                                 \
        _Pragma("unroll")                                                             \
        for (int i = 0; i < 4; i++) {                                                 \
            int idx = i * 256 + tid;                                                  \
            int r = idx >> 4, c = idx & 15;                                           \
            uint32_t dp = sbase + (uint32_t)(AT_KS + (bf) * 64 * 68 + r * 68 + c * 4) * 4; \
            CP_ASYNC16(dp, KL + ((size_t)bh * S_LEN + (ci) * 64 + r) * LDIM + c * 4); \
        }                                                                             \
        _Pragma("unroll")                                                             \
        for (int i = 0; i < 8; i++) {                                                 \
            int idx = i * 256 + tid;                                                  \
            int r = idx >> 5, c = idx & 31;                                           \
            uint32_t dp = sbase + (uint32_t)(AT_VS + (bf) * 64 * 136 + r * 136 + c * 4) * 4; \
            CP_ASYNC16(dp, V + ((size_t)(b * S_LEN + (ci) * 64 + r)) * E_DIM + h * DH + c * 4); \
        }                                                                             \
    }

    AT_PREFETCH(0, 0)
    CP_COMMIT();

    float ot[16][4], ob[16][4];
#pragma unroll
    for (int n = 0; n < 16; n++)
#pragma unroll
        for (int j = 0; j < 4; j++) { ot[n][j] = 0.f; ob[n][j] = 0.f; }
    float l0 = 0.f, l1 = 0.f;

    for (int ci = 0; ci < 32; ci++) {
        int buf = ci & 1;
        CP_WAIT(0);
        __syncthreads();
        if (ci < 31) {
            AT_PREFETCH(ci + 1, buf ^ 1)
            CP_COMMIT();
        }
        const float* ks  = ksb + buf * 64 * 68;
        const float* vsx = vsb + buf * 64 * 136;

        float c[8][4];
#pragma unroll
        for (int n = 0; n < 8; n++)
#pragma unroll
            for (int j = 0; j < 4; j++) c[n][j] = 0.f;
#pragma unroll
        for (int kk = 0; kk < 8; kk++) {
            int ko = kk * 8 + t;
            uint32_t a0 = __float_as_uint(qs[(wrow + g) * 68 + ko]);
            uint32_t a1 = __float_as_uint(qs[(wrow + 8 + g) * 68 + ko]);
            uint32_t a2 = __float_as_uint(qs[(wrow + g) * 68 + ko + 4]);
            uint32_t a3 = __float_as_uint(qs[(wrow + 8 + g) * 68 + ko + 4]);
#pragma unroll
            for (int n = 0; n < 8; n++) {
                uint32_t b0 = __float_as_uint(ks[(n * 8 + g) * 68 + ko]);
                uint32_t b1 = __float_as_uint(ks[(n * 8 + g) * 68 + ko + 4]);
                MMA_TF32(c[n], a0, a1, a2, a3, b0, b1);
            }
        }
#pragma unroll
        for (int n = 0; n < 8; n++) {
            float p0 = __expf(c[n][0]), p1 = __expf(c[n][1]);
            float p2 = __expf(c[n][2]), p3 = __expf(c[n][3]);
            l0 += p0 + p1; l1 += p2 + p3;
            float2 u0 = make_float2(tf32r(p0), tf32r(p1));
            float2 u1 = make_float2(tf32r(p2), tf32r(p3));
            *reinterpret_cast<float2*>(&Ps[(wrow + g) * 68 + n * 8 + 2 * t]) = u0;
            *reinterpret_cast<float2*>(&Ps[(wrow + 8 + g) * 68 + n * 8 + 2 * t]) = u1;
        }
        __syncthreads();
#pragma unroll
        for (int kk = 0; kk < 8; kk++) {
            int ko = kk * 8 + t;
            uint32_t a0 = __float_as_uint(Ps[(wrow + g) * 68 + ko]);
            uint32_t a1 = __float_as_uint(Ps[(wrow + 8 + g) * 68 + ko]);
            uint32_t a2 = __float_as_uint(Ps[(wrow + g) * 68 + ko + 4]);
            uint32_t a3 = __float_as_uint(Ps[(wrow + 8 + g) * 68 + ko + 4]);
#pragma unroll
            for (int n = 0; n < 16; n++) {
                uint32_t b0 = __float_as_uint(vsx[ko * 136 + n * 8 + g]);
                uint32_t b1 = __float_as_uint(vsx[(ko + 4) * 136 + n * 8 + g]);
                MMA_TF32(ob[n], a0, a1, a2, a3, b0, b1);
            }
        }
        if ((ci & 7) == 7) {
            l0 += __shfl_xor_sync(0xFFFFFFFFu, l0, 1);
            l0 += __shfl_xor_sync(0xFFFFFFFFu, l0, 2);
            l1 += __shfl_xor_sync(0xFFFFFFFFu, l1, 1);
            l1 += __shfl_xor_sync(0xFFFFFFFFu, l1, 2);
            float i0 = 1.f / l0, i1 = 1.f / l1;
#pragma unroll
            for (int n = 0; n < 16; n++) {
                ot[n][0] += ob[n][0] * i0; ot[n][1] += ob[n][1] * i0;
                ot[n][2] += ob[n][2] * i1; ot[n][3] += ob[n][3] * i1;
                ob[n][0] = 0.f; ob[n][1] = 0.f; ob[n][2] = 0.f; ob[n][3] = 0.f;
            }
            l0 = 0.f; l1 = 0.f;
        }
    }
#undef AT_PREFETCH

    {
        size_t row0 = (size_t)bh * S_LEN + qb * 128 + wrow + g;
#pragma unroll
        for (int n = 0; n < 16; n++) {
            __nv_bfloat16 h0, l0b, h1, l1b;
            bf16_split(ot[n][0], h0, l0b); bf16_split(ot[n][1], h1, l1b);
            size_t o0 = row0 * DH + n * 8 + 2 * t;
            *reinterpret_cast<__nv_bfloat162*>(&OUThi[o0]) = __nv_bfloat162(h0, h1);
            *reinterpret_cast<__nv_bfloat162*>(&OUTlo[o0]) = __nv_bfloat162(l0b, l1b);
            bf16_split(ot[n][2], h0, l0b); bf16_split(ot[n][3], h1, l1b);
            size_t o1 = (row0 + 8) * DH + n * 8 + 2 * t;
            *reinterpret_cast<__nv_bfloat162*>(&OUThi[o1]) = __nv_bfloat162(h0, h1);
            *reinterpret_cast<__nv_bfloat162*>(&OUTlo[o1]) = __nv_bfloat162(l0b, l1b);
        }
    }
}

// ---------------- mixer: gelu(AT @ Wm + bm), bf16 3-term, fused transpose+split ----------------
#define MX_AEL (128 * 136)
#define MX_SMEM (4 * MX_AEL * 2)

__global__ __launch_bounds__(256) void mixer_bf16_kernel(
    const __nv_bfloat16* __restrict__ AThi, const __nv_bfloat16* __restrict__ ATlo,
    const __nv_bfloat16* __restrict__ Wmhi, const __nv_bfloat16* __restrict__ Wmlo,
    const float* __restrict__ bm,
    __nv_bfloat16* __restrict__ Ohi, __nv_bfloat16* __restrict__ Olo)
{
    extern __shared__ __nv_bfloat16 smb[];
    __nv_bfloat16* Ah = smb;
    __nv_bfloat16* Al = Ah + MX_AEL;
    __nv_bfloat16* Bh = Al + MX_AEL;
    __nv_bfloat16* Bl = Bh + MX_AEL;

    int tid = threadIdx.x, w = tid >> 5, lane = tid & 31;
    int wr = w >> 2, wc = w & 3;
    int m0 = blockIdx.x * 128;

#pragma unroll
    for (int i = 0; i < 8; i++) {
        int idx = i * 256 + tid;
        int r = idx >> 4, c8 = idx & 15;
        *reinterpret_cast<uint4*>(&Ah[r * 136 + c8 * 8]) =
            *reinterpret_cast<const uint4*>(&AThi[(size_t)(m0 + r) * DH + c8 * 8]);
        *reinterpret_cast<uint4*>(&Al[r * 136 + c8 * 8]) =
            *reinterpret_cast<const uint4*>(&ATlo[(size_t)(m0 + r) * DH + c8 * 8]);
        *reinterpret_cast<uint4*>(&Bh[r * 136 + c8 * 8]) =
            *reinterpret_cast<const uint4*>(&Wmhi[r * DH + c8 * 8]);
        *reinterpret_cast<uint4*>(&Bl[r * 136 + c8 * 8]) =
            *reinterpret_cast<const uint4*>(&Wmlo[r * DH + c8 * 8]);
    }
    __syncthreads();

    wmma::fragment<wmma::accumulator, 16, 16, 16, float> cf[4][2];
#pragma unroll
    for (int i = 0; i < 4; i++)
#pragma unroll
        for (int j = 0; j < 2; j++) wmma::fill_fragment(cf[i][j], 0.f);

#pragma unroll
    for (int ks = 0; ks < 8; ks++) {
        wmma::fragment<wmma::matrix_a, 16, 16, 16, __nv_bfloat16, wmma::row_major> ah[4], al2[4];
        wmma::fragment<wmma::matrix_b, 16, 16, 16, __nv_bfloat16, wmma::col_major> bh[2], bl2[2];
#pragma unroll
        for (int i = 0; i < 4; i++) {
            wmma::load_matrix_sync(ah[i], &Ah[(wr * 64 + i * 16) * 136 + ks * 16], 136);
            wmma::load_matrix_sync(al2[i], &Al[(wr * 64 + i * 16) * 136 + ks * 16], 136);
        }
#pragma unroll
        for (int j = 0; j < 2; j++) {
            wmma::load_matrix_sync(bh[j], &Bh[(wc * 32 + j * 16) * 136 + ks * 16], 136);
            wmma::load_matrix_sync(bl2[j], &Bl[(wc * 32 + j * 16) * 136 + ks * 16], 136);
        }
#pragma unroll
        for (int i = 0; i < 4; i++)
#pragma unroll
            for (int j = 0; j < 2; j++) {
                wmma::mma_sync(cf[i][j], ah[i], bl2[j], cf[i][j]);
                wmma::mma_sync(cf[i][j], al2[i], bh[j], cf[i][j]);
                wmma::mma_sync(cf[i][j], ah[i], bh[j], cf[i][j]);
            }
    }
    __syncthreads();

    float* scratch = reinterpret_cast<float*>(smb) + w * 320;
#pragma unroll
    for (int i = 0; i < 4; i++)
#pragma unroll
        for (int j = 0; j < 2; j++) {
            wmma::store_matrix_sync(scratch, cf[i][j], 20, wmma::mem_row_major);
            __syncwarp();
#pragma unroll
            for (int e = lane; e < 256; e += 32) {
                int rr = e >> 4, cc = e & 15;
                int rg = m0 + wr * 64 + i * 16 + rr;
                int gc = wc * 32 + j * 16 + cc;
                float v = gelu_tanh(scratch[rr * 20 + cc] + bm[gc]);
                int bb = rg >> 15;
                int hh = (rg >> 11) & 15;
                int ss = rg & 2047;
                size_t o = ((size_t)(bb * S_LEN + ss)) * E_DIM + hh * DH + gc;
                __nv_bfloat16 hv, lv;
                bf16_split(v, hv, lv);
                Ohi[o] = hv; Olo[o] = lv;
            }
            __syncwarp();
        }
}

// ---------------- launch ----------------
extern "C" void kernel_launch(void* const* d_in, const int* in_sizes, int n_in,
                              void* d_out, int out_size)
{
    const float* x   = (const float*)d_in[0];
    const float* Wq  = (const float*)d_in[1];
    const float* bq  = (const float*)d_in[2];
    const float* Wk  = (const float*)d_in[3];
    const float* bk  = (const float*)d_in[4];
    const float* Wv  = (const float*)d_in[5];
    const float* bv  = (const float*)d_in[6];
    const float* Wo  = (const float*)d_in[7];
    const float* bo  = (const float*)d_in[8];
    const float* Wql = (const float*)d_in[9];
    const float* bql = (const float*)d_in[10];
    const float* Wkl = (const float*)d_in[11];
    const float* bkl = (const float*)d_in[12];
    const float* Wm  = (const float*)d_in[13];
    const float* bm  = (const float*)d_in[14];
    float* out = (float*)d_out;

    float *pV, *pQL, *pKL;
    __nv_bfloat16 *pAhi, *pAlo, *pQhi, *pQlo, *pKhi, *pKlo;
    __nv_bfloat16 *pW3hi, *pW3lo, *pWthi, *pWtlo;
    __nv_bfloat16 *pAThi, *pATlo, *pWmhi, *pWmlo, *pWlhi, *pWllo;
    cudaGetSymbolAddress((void**)&pV,   g_V);
    cudaGetSymbolAddress((void**)&pQL,  g_QL);
    cudaGetSymbolAddress((void**)&pKL,  g_KL);
    cudaGetSymbolAddress((void**)&pAhi, g_Ahi);
    cudaGetSymbolAddress((void**)&pAlo, g_Alo);
    cudaGetSymbolAddress((void**)&pQhi, g_Qhi);
    cudaGetSymbolAddress((void**)&pQlo, g_Qlo);
    cudaGetSymbolAddress((void**)&pKhi, g_Khi);
    cudaGetSymbolAddress((void**)&pKlo, g_Klo);
    cudaGetSymbolAddress((void**)&pW3hi, g_W3hi);
    cudaGetSymbolAddress((void**)&pW3lo, g_W3lo);
    cudaGetSymbolAddress((void**)&pWthi, g_Wthi);
    cudaGetSymbolAddress((void**)&pWtlo, g_Wtlo);
    cudaGetSymbolAddress((void**)&pAThi, g_AThi);
    cudaGetSymbolAddress((void**)&pATlo, g_ATlo);
    cudaGetSymbolAddress((void**)&pWmhi, g_Wmhi);
    cudaGetSymbolAddress((void**)&pWmlo, g_Wmlo);
    cudaGetSymbolAddress((void**)&pWlhi, g_Wlhi);
    cudaGetSymbolAddress((void**)&pWllo, g_Wllo);

    cudaFuncSetAttribute(attn2_kernel, cudaFuncAttributeMaxDynamicSharedMemorySize, AT_SMEM_B);
    cudaFuncSetAttribute(gemm_qkv_kernel, cudaFuncAttributeMaxDynamicSharedMemorySize, GN_SMEM);
    cudaFuncSetAttribute(gemm_bf3_kernel, cudaFuncAttributeMaxDynamicSharedMemorySize, GN_SMEM);
    cudaFuncSetAttribute(lat_bf16_kernel, cudaFuncAttributeMaxDynamicSharedMemorySize, LB_SMEM);
    cudaFuncSetAttribute(mixer_bf16_kernel, cudaFuncAttributeMaxDynamicSharedMemorySize, MX_SMEM);

    const int n4 = (M_ROWS * E_DIM) / 4;

    xsplit_kernel<<<(n4 + 255) / 256, 256>>>(x, pAhi, pAlo, n4);
    wsplit4_kernel<<<dim3(64, 64, 4), 256>>>(Wq, Wk, Wv, Wo, pW3hi, pW3lo, pWthi, pWtlo);
    smallw_kernel<<<3, 256>>>(Wm, Wql, Wkl, pWmhi, pWmlo, pWlhi, pWllo);

    gemm_qkv_kernel<<<dim3(48, 16), 256, GN_SMEM>>>(
        pAhi, pAlo, pW3hi, pW3lo, bq, bk, bv, pQhi, pQlo, pKhi, pKlo, pV);

    lat_bf16_kernel<<<dim3(32, 16, 2), 256, LB_SMEM>>>(
        pQhi, pQlo, pKhi, pKlo, pWlhi, pWllo, bql, bkl, pQL, pKL);

    attn2_kernel<<<dim3(16, 16, 2), 256, AT_SMEM_B>>>(pQL, pKL, pV, pAThi, pATlo);

    mixer_bf16_kernel<<<dim3(512), 256, MX_SMEM>>>(pAThi, pATlo, pWmhi, pWmlo, bm, pAhi, pAlo);

    gemm_bf3_kernel<<<dim3(16, 16), 256, GN_SMEM>>>(pAhi, pAlo, pWthi, pWtlo, bo, out);
}